// round 9
// baseline (speedup 1.0000x reference)
#include <cuda_runtime.h>

#define TDIM 200
#define PDIM 784
#define BDIM 256
#define PSPLIT 16
#define PCHUNK 49     // 784 / 16
#define BTILE 8
#define PI_F 3.14159265358979323846f

typedef unsigned long long ull;

// Scratch (no allocation allowed)
__device__ float2 g_c[TDIM];
__device__ __align__(16) float2 g_Dt[TDIM * TDIM];   // [t][f], imag NEGATED, /T
__device__ __align__(16) float2 g_u[PSPLIT][BDIM * TDIM];  // p-split partials
__device__ __align__(16) float2 g_ured[BDIM * TDIM];       // reduced u

// ---- packed f32x2 helpers ------------------------------------------------
__device__ __forceinline__ ull pk2(float x, float y) {
    ull r; asm("mov.b64 %0, {%1, %2};" : "=l"(r) : "f"(x), "f"(y)); return r;
}
__device__ __forceinline__ void upk2(ull v, float& x, float& y) {
    asm("mov.b64 {%0, %1}, %2;" : "=f"(x), "=f"(y) : "l"(v));
}
__device__ __forceinline__ void fma2(ull& acc, ull a, ull b) {
    asm("fma.rn.f32x2 %0, %1, %2, %0;" : "+l"(acc) : "l"(a), "l"(b));
}

// ---------------------------------------------------------------------------
// K1 (fused): blocks (s<16, by): u[b][f] = sum_p xv[b][p] * S[p][f] (complex)
//             block  (s==16, by==0): c[f] = DFT(waveform)[f] * env[f]
// grid (17, 32) = 544 blocks, block 200 (f). FULLY UNROLLED mainloop:
// all LDG/LDS use immediate offsets, no IMADs, no reg copies, no branches.
// ---------------------------------------------------------------------------
__global__ void __launch_bounds__(TDIM) k_uc(const float* __restrict__ x,
                                             const float* __restrict__ v,
                                             const float* __restrict__ sre,
                                             const float* __restrict__ sim,
                                             const float* __restrict__ wre,
                                             const float* __restrict__ wim,
                                             const float* __restrict__ ere,
                                             const float* __restrict__ eim) {
    __shared__ __align__(16) float2 xv_s[PCHUNK][BTILE];  // (a, a) packed
    __shared__ float2 tw[TDIM];
    __shared__ float wr_s[TDIM], wi_s[TDIM];

    const int s   = blockIdx.x;
    const int tid = threadIdx.x;

    if (s == PSPLIT) {
        // ---- c[f] branch: one block, 200-point DFT via shared twiddles ----
        if (blockIdx.y != 0) return;
        const int f = tid;
        {
            float ang = (2.0f * PI_F / TDIM) * (float)f;
            float si, co;
            sincosf(ang, &si, &co);
            tw[f] = make_float2(co, si);
            wr_s[f] = wre[f];
            wi_s[f] = wim[f];
        }
        __syncthreads();
        float ar = 0.f, ai = 0.f;
        int m = 0;  // (f*t) mod 200 exact
        for (int t = 0; t < TDIM; t++) {
            float2 w = tw[m];
            m += f; if (m >= TDIM) m -= TDIM;
            float xr = wr_s[t], xi = wi_s[t];
            ar += xr * w.x + xi * w.y;   // x * e^{-i ang}
            ai += xi * w.x - xr * w.y;
        }
        float er = ere[f], ei = eim[f];
        g_c[f] = make_float2(ar * er - ai * ei, ar * ei + ai * er);
        return;
    }

    // ---- u branch ----
    const int b0 = blockIdx.y * BTILE;
    const int p0 = s * PCHUNK;

    for (int idx = tid; idx < PCHUNK * BTILE; idx += TDIM) {
        int pp = idx >> 3, j = idx & 7;
        float a = x[(b0 + j) * PDIM + p0 + pp] * v[p0 + pp];
        xv_s[pp][j] = make_float2(a, a);
    }
    __syncthreads();

    const int f = tid;
    ull acc[BTILE];   // acc[j] = packed (u_re, u_im) for batch b0+j
#pragma unroll
    for (int j = 0; j < BTILE; j++) acc[j] = 0ull;

    const float* srp = sre + (size_t)p0 * TDIM + f;
    const float* sip = sim + (size_t)p0 * TDIM + f;
    const ulonglong2* xvb = (const ulonglong2*)xv_s;   // 4 per row

#pragma unroll
    for (int pp = 0; pp < PCHUNK; pp++) {
        float r_ = srp[pp * TDIM];      // [R+imm] LDG, compiler-scheduled
        float i_ = sip[pp * TDIM];
        ull bpk = pk2(r_, i_);          // (sre, sim)
#pragma unroll
        for (int q = 0; q < 4; q++) {
            ulonglong2 a = xvb[pp * 4 + q];   // LDS.128 imm offset, mov-free
            fma2(acc[2 * q + 0], a.x, bpk);   // batch 2q
            fma2(acc[2 * q + 1], a.y, bpk);   // batch 2q+1
        }
    }
#pragma unroll
    for (int j = 0; j < BTILE; j++) {
        float ur, ui_;
        upk2(acc[j], ur, ui_);
        g_u[s][(b0 + j) * TDIM + f] = make_float2(ur, ui_);
    }
}

// ---------------------------------------------------------------------------
// K2 (fused): grid 256, block 200.
//   blocks 0..199:  D^T[t][f] = (Re, -Im) of c[f] * e^{+2pi i f t/T} / T
//   ALL blocks b:   g_ured[b][f] = sum_s g_u[s][b][f]   (16-way reduce)
// ---------------------------------------------------------------------------
__global__ void __launch_bounds__(TDIM) k_Dred() {
    const int blk = blockIdx.x, f = threadIdx.x;

    // reduction part: one batch per block
    {
        float2 a = make_float2(0.f, 0.f);
        const int base = blk * TDIM + f;
#pragma unroll
        for (int s = 0; s < PSPLIT; s++) {
            float2 p = g_u[s][base];
            a.x += p.x; a.y += p.y;
        }
        g_ured[base] = a;
    }

    // D part: blocks 0..199
    if (blk < TDIM) {
        const int t = blk;
        int m = (f * t) % TDIM;
        float ang = (2.0f * PI_F / TDIM) * (float)m;
        float si, co;
        sincosf(ang, &si, &co);
        float2 c = g_c[f];
        const float inv = 1.0f / TDIM;
        g_Dt[t * TDIM + f] = make_float2((c.x * co - c.y * si) * inv,
                                         -(c.x * si + c.y * co) * inv);
    }
}

// ---------------------------------------------------------------------------
// K3: r[b][t] = Re(sum_f u[b][f]*D[f][t]); chunk-max; 10x10 linear
// grid 128 blocks (full chip), block 200 (t); 2 batches per thread off ONE
// D-row stream. All FFMA2 operands mov-free (ulonglong2 from LDG/LDS).
// ---------------------------------------------------------------------------
__global__ void __launch_bounds__(TDIM) k_out(const float* __restrict__ lw,
                                              const float* __restrict__ lb,
                                              float* __restrict__ out) {
    __shared__ __align__(16) float2 u_s[2][TDIM];
    __shared__ float vals[2][TDIM];
    __shared__ float cm[2][10];
    const int t  = threadIdx.x;
    const int b0 = blockIdx.x * 2;

    u_s[0][t] = g_ured[(b0 + 0) * TDIM + t];
    u_s[1][t] = g_ured[(b0 + 1) * TDIM + t];
    __syncthreads();

    const ulonglong2* dp = (const ulonglong2*)(g_Dt + (size_t)t * TDIM);
    const ulonglong2* u0 = (const ulonglong2*)u_s[0];
    const ulonglong2* u1 = (const ulonglong2*)u_s[1];
    ull a0 = 0, a1 = 0, b0a = 0, b1a = 0;
#pragma unroll 10
    for (int j = 0; j < TDIM / 2; j++) {
        ulonglong2 d  = dp[j];   // .x=(dre,-dim)@2j  .y=@2j+1  (LDG.128)
        ulonglong2 w0 = u0[j];   // .x=(ure,uim)@2j   (LDS.128 broadcast)
        ulonglong2 w1 = u1[j];
        fma2(a0, w0.x, d.x);  fma2(b0a, w0.y, d.y);
        fma2(a1, w1.x, d.x);  fma2(b1a, w1.y, d.y);
    }
    {
        float x0, y0, x1, y1;
        upk2(a0, x0, y0); upk2(b0a, x1, y1);
        float r = (x0 + y0) + (x1 + y1);   // sum(ure*dre - uim*dim)
        vals[0][t] = sqrtf(fmaf(r, r, 1e-20f));
        upk2(a1, x0, y0); upk2(b1a, x1, y1);
        r = (x0 + y0) + (x1 + y1);
        vals[1][t] = sqrtf(fmaf(r, r, 1e-20f));
    }
    __syncthreads();

    if (t < 20) {
        int bb = t / 10, c = t % 10;
        float mx = 0.f;
#pragma unroll
        for (int k = 0; k < 20; k++) mx = fmaxf(mx, vals[bb][c * 20 + k]);
        cm[bb][c] = mx;
    }
    __syncthreads();

    if (t < 20) {
        int bb = t / 10, c = t % 10;
        float o = lb[c];
#pragma unroll
        for (int cc = 0; cc < 10; cc++) o = fmaf(cm[bb][cc], lw[c * 10 + cc], o);
        out[(b0 + bb) * 10 + c] = o;
    }
}

// ---------------------------------------------------------------------------
extern "C" void kernel_launch(void* const* d_in, const int* in_sizes, int n_in,
                              void* d_out, int out_size) {
    const float* x   = (const float*)d_in[0];  // [256, 784]
    const float* v   = (const float*)d_in[1];  // [784]
    const float* sre = (const float*)d_in[2];  // [784, 200]
    const float* sim = (const float*)d_in[3];  // [784, 200]
    const float* ere = (const float*)d_in[4];  // [200]
    const float* eim = (const float*)d_in[5];  // [200]
    const float* wre = (const float*)d_in[6];  // [200]
    const float* wim = (const float*)d_in[7];  // [200]
    const float* lw  = (const float*)d_in[8];  // [10, 10]
    const float* lb  = (const float*)d_in[9];  // [10]
    float* out = (float*)d_out;                // [256, 10] float32

    k_uc<<<dim3(PSPLIT + 1, BDIM / BTILE), TDIM>>>(x, v, sre, sim,
                                                   wre, wim, ere, eim);
    k_Dred<<<BDIM, TDIM>>>();
    k_out<<<BDIM / 2, TDIM>>>(lw, lb, out);
}

// round 10
// speedup vs baseline: 1.5169x; 1.5169x over previous
#include <cuda_runtime.h>

#define TDIM 200
#define PDIM 784
#define BDIM 256
#define PSPLIT 8
#define PCHUNK 98     // 784 / 8
#define BTILE 8
#define PI_F 3.14159265358979323846f

typedef unsigned long long ull;

// Scratch (no allocation allowed)
__device__ float2 g_c[TDIM];
__device__ __align__(16) float2 g_Dt[TDIM * TDIM];   // [t][f], imag NEGATED, /T
__device__ __align__(16) float2 g_u[PSPLIT][BDIM * TDIM];  // p-split partials

// ---- packed f32x2 helpers ------------------------------------------------
__device__ __forceinline__ ull pk2(float x, float y) {
    ull r; asm("mov.b64 %0, {%1, %2};" : "=l"(r) : "f"(x), "f"(y)); return r;
}
__device__ __forceinline__ void upk2(ull v, float& x, float& y) {
    asm("mov.b64 {%0, %1}, %2;" : "=f"(x), "=f"(y) : "l"(v));
}
__device__ __forceinline__ void fma2(ull& acc, ull a, ull b) {
    asm("fma.rn.f32x2 %0, %1, %2, %0;" : "+l"(acc) : "l"(a), "l"(b));
}

// ---------------------------------------------------------------------------
// K1 (fused): blocks (s<8, by): u[b][f] = sum_p xv[b][p] * S[p][f]  (complex)
//             block  (s==8, by==0): c[f] = DFT(waveform)[f] * env[f]
// grid (9, 32) = 288 blocks (~2/SM), block 200 threads (f), 8 batches/block.
// Explicit 2-deep software pipeline (G=7): keeps 14 LDGs in flight (regs ~72).
// ---------------------------------------------------------------------------
__global__ void __launch_bounds__(TDIM) k_uc(const float* __restrict__ x,
                                             const float* __restrict__ v,
                                             const float* __restrict__ sre,
                                             const float* __restrict__ sim,
                                             const float* __restrict__ wre,
                                             const float* __restrict__ wim,
                                             const float* __restrict__ ere,
                                             const float* __restrict__ eim) {
    __shared__ __align__(16) float2 xv_s[PCHUNK][BTILE];  // (a, a) packed
    __shared__ float2 tw[TDIM];
    __shared__ float wr_s[TDIM], wi_s[TDIM];

    const int s   = blockIdx.x;
    const int tid = threadIdx.x;

    if (s == PSPLIT) {
        // ---- c[f] branch: one block, 200-point DFT via shared twiddles ----
        if (blockIdx.y != 0) return;
        const int f = tid;
        {
            float ang = (2.0f * PI_F / TDIM) * (float)f;
            float si, co;
            sincosf(ang, &si, &co);
            tw[f] = make_float2(co, si);
            wr_s[f] = wre[f];
            wi_s[f] = wim[f];
        }
        __syncthreads();
        float ar = 0.f, ai = 0.f;
        int m = 0;  // (f*t) mod 200 exact
        for (int t = 0; t < TDIM; t++) {
            float2 w = tw[m];
            m += f; if (m >= TDIM) m -= TDIM;
            float xr = wr_s[t], xi = wi_s[t];
            ar += xr * w.x + xi * w.y;   // x * e^{-i ang}
            ai += xi * w.x - xr * w.y;
        }
        float er = ere[f], ei = eim[f];
        g_c[f] = make_float2(ar * er - ai * ei, ar * ei + ai * er);
        return;
    }

    // ---- u branch ----
    const int b0 = blockIdx.y * BTILE;
    const int p0 = s * PCHUNK;

    // coalesced prologue: consecutive tid -> consecutive p within one batch row
    for (int idx = tid; idx < PCHUNK * BTILE; idx += TDIM) {
        int j = idx / PCHUNK, pp = idx % PCHUNK;
        float a = x[(b0 + j) * PDIM + p0 + pp] * v[p0 + pp];
        xv_s[pp][j] = make_float2(a, a);
    }
    __syncthreads();

    const int f = tid;
    ull acc[BTILE];   // acc[j] = packed (u_re, u_im) for batch b0+j
#pragma unroll
    for (int j = 0; j < BTILE; j++) acc[j] = 0ull;

    const float* srp = sre + (size_t)p0 * TDIM + f;
    const float* sip = sim + (size_t)p0 * TDIM + f;

    const int G = 7;  // 14 groups of 7 (98 = 7*14), software pipelined
    float cre[G], cim[G], nre[G], nim[G];
#pragma unroll
    for (int k = 0; k < G; k++) {
        cre[k] = srp[(size_t)k * TDIM];
        cim[k] = sip[(size_t)k * TDIM];
    }
    for (int g = 0; g < 14; g++) {
        if (g < 13) {
            int base = (g + 1) * G;
#pragma unroll
            for (int k = 0; k < G; k++) {
                nre[k] = srp[(size_t)(base + k) * TDIM];
                nim[k] = sip[(size_t)(base + k) * TDIM];
            }
        }
        const int pb = g * G;
#pragma unroll
        for (int k = 0; k < G; k++) {
            ull bpk = pk2(cre[k], cim[k]);               // (sre, sim)
            const ulonglong2* xv2 = (const ulonglong2*)xv_s[pb + k];
            // row = 8 packed float2 = 4 ulonglong2; .x -> batch 2q, .y -> 2q+1
#pragma unroll
            for (int q = 0; q < 4; q++) {
                ulonglong2 a = xv2[q];                    // LDS.128 broadcast
                fma2(acc[2 * q + 0], a.x, bpk);
                fma2(acc[2 * q + 1], a.y, bpk);
            }
        }
#pragma unroll
        for (int k = 0; k < G; k++) { cre[k] = nre[k]; cim[k] = nim[k]; }
    }
#pragma unroll
    for (int j = 0; j < BTILE; j++) {
        float ur, ui_;
        upk2(acc[j], ur, ui_);
        g_u[s][(b0 + j) * TDIM + f] = make_float2(ur, ui_);
    }
}

// ---------------------------------------------------------------------------
// K2: D^T[t][f] = (Re, -Im) of c[f] * e^{+2pi i f t/T} / T
// grid 200 (t), block 200 (f): fully coalesced float2 stores
// ---------------------------------------------------------------------------
__global__ void __launch_bounds__(TDIM) k_D() {
    const int t = blockIdx.x, f = threadIdx.x;
    int m = (f * t) % TDIM;
    float ang = (2.0f * PI_F / TDIM) * (float)m;
    float si, co;
    sincosf(ang, &si, &co);
    float2 c = g_c[f];
    const float inv = 1.0f / TDIM;
    g_Dt[t * TDIM + f] = make_float2((c.x * co - c.y * si) * inv,
                                     -(c.x * si + c.y * co) * inv);
}

// ---------------------------------------------------------------------------
// K3: r[b][t] = Re(sum_f u[b][f]*D[f][t]); chunk-max; 10x10 linear
// grid 128 blocks (full chip), block 200 (t); 2 batches per thread off ONE
// D-row stream; 8-way partial gather. Mov-free FFMA2 (ulonglong2 operands).
// ---------------------------------------------------------------------------
__global__ void __launch_bounds__(TDIM) k_out(const float* __restrict__ lw,
                                              const float* __restrict__ lb,
                                              float* __restrict__ out) {
    __shared__ __align__(16) float2 u_s[2][TDIM];
    __shared__ float vals[2][TDIM];
    __shared__ float cm[2][10];
    const int t  = threadIdx.x;
    const int b0 = blockIdx.x * 2;

    // gather + reduce the 8 p-split partials of u for both batches
#pragma unroll
    for (int bb = 0; bb < 2; bb++) {
        float2 a = make_float2(0.f, 0.f);
#pragma unroll
        for (int s = 0; s < PSPLIT; s++) {
            float2 p = g_u[s][(b0 + bb) * TDIM + t];
            a.x += p.x; a.y += p.y;
        }
        u_s[bb][t] = a;
    }
    __syncthreads();

    const ulonglong2* dp = (const ulonglong2*)(g_Dt + (size_t)t * TDIM);
    const ulonglong2* u0 = (const ulonglong2*)u_s[0];
    const ulonglong2* u1 = (const ulonglong2*)u_s[1];
    ull a0 = 0, a1 = 0, b0a = 0, b1a = 0;
#pragma unroll 10
    for (int j = 0; j < TDIM / 2; j++) {
        ulonglong2 d  = dp[j];   // .x=(dre,-dim)@2j  .y=@2j+1  (LDG.128)
        ulonglong2 w0 = u0[j];   // .x=(ure,uim)@2j   (LDS.128 broadcast)
        ulonglong2 w1 = u1[j];
        fma2(a0, w0.x, d.x);  fma2(b0a, w0.y, d.y);
        fma2(a1, w1.x, d.x);  fma2(b1a, w1.y, d.y);
    }
    {
        float x0, y0, x1, y1;
        upk2(a0, x0, y0); upk2(b0a, x1, y1);
        float r = (x0 + y0) + (x1 + y1);   // sum(ure*dre - uim*dim)
        vals[0][t] = sqrtf(fmaf(r, r, 1e-20f));
        upk2(a1, x0, y0); upk2(b1a, x1, y1);
        r = (x0 + y0) + (x1 + y1);
        vals[1][t] = sqrtf(fmaf(r, r, 1e-20f));
    }
    __syncthreads();

    if (t < 20) {
        int bb = t / 10, c = t % 10;
        float mx = 0.f;
#pragma unroll
        for (int k = 0; k < 20; k++) mx = fmaxf(mx, vals[bb][c * 20 + k]);
        cm[bb][c] = mx;
    }
    __syncthreads();

    if (t < 20) {
        int bb = t / 10, c = t % 10;
        float o = lb[c];
#pragma unroll
        for (int cc = 0; cc < 10; cc++) o = fmaf(cm[bb][cc], lw[c * 10 + cc], o);
        out[(b0 + bb) * 10 + c] = o;
    }
}

// ---------------------------------------------------------------------------
extern "C" void kernel_launch(void* const* d_in, const int* in_sizes, int n_in,
                              void* d_out, int out_size) {
    const float* x   = (const float*)d_in[0];  // [256, 784]
    const float* v   = (const float*)d_in[1];  // [784]
    const float* sre = (const float*)d_in[2];  // [784, 200]
    const float* sim = (const float*)d_in[3];  // [784, 200]
    const float* ere = (const float*)d_in[4];  // [200]
    const float* eim = (const float*)d_in[5];  // [200]
    const float* wre = (const float*)d_in[6];  // [200]
    const float* wim = (const float*)d_in[7];  // [200]
    const float* lw  = (const float*)d_in[8];  // [10, 10]
    const float* lb  = (const float*)d_in[9];  // [10]
    float* out = (float*)d_out;                // [256, 10] float32

    k_uc<<<dim3(PSPLIT + 1, BDIM / BTILE), TDIM>>>(x, v, sre, sim,
                                                   wre, wim, ere, eim);
    k_D<<<TDIM, TDIM>>>();
    k_out<<<BDIM / 2, TDIM>>>(lw, lb, out);
}